// round 14
// baseline (speedup 1.0000x reference)
#include <cuda_runtime.h>
#include <cuda_bf16.h>
#include <math.h>
#include <stdint.h>

// ---------------------------------------------------------------------------
// Problem constants
// ---------------------------------------------------------------------------
#define S_LEN   8192
#define HID     2048
#define NH      16
#define HD      128
#define CHK     64
#define NCH     128           // S / CHK
#define HDTOT   2048
#define QKV_N   6144
#define MEGA_N  8192          // qkv (6144) + gate (2048) merged
#define EPS     1e-5f
#define SCALE_Q 0.08838834764831845f

// split-K GEMM constants (round-11 proven: 3-plane physical storage)
#define GK      6144
#define BKG     64
#define NSTEP   96
#define GSTG    3
#define STAGE_BYTES (128*BKG*2 + 128*BKG*2)   // 32768
#define GEMM_SMEM   (GSTG * STAGE_BYTES)      // 98304

// attention smem: 2-plane operands, no aliasing, single load phase
#define Q2_ROW 528
#define V2_ROW 272
#define A2_SQ  0
#define A2_SS  33792
#define A2_SK  (A2_SS + 128*528)   // 101376
#define A2_SV  (A2_SK + 64*528)    // 135168
#define A2_SP  (A2_SV + 128*272)   // 169984
#define A2_TBL (A2_SP + 64*528)    // 203776
#define ATTN_SMEM (A2_TBL + 288)   // 204064

// chunk_kv smem (2-plane)
#define C2_K 0
#define C2_V 34816
#define CHUNK_SMEM 69632

// ---------------------------------------------------------------------------
// Scratch (static device globals; no allocation allowed)
// ---------------------------------------------------------------------------
__device__ float d_attn[ (size_t)S_LEN * HDTOT ];
__device__ float d_g   [ (size_t)S_LEN * HDTOT ];
__device__ float d_kvc [ (size_t)NCH * NH * HD * HD ];

__device__ __nv_bfloat16 d_hs_s [ (size_t)S_LEN * GK ];
__device__ __nv_bfloat16 d_bw_s [ (size_t)MEGA_N * GK ];   // qkv_w (6144 rows) + g_w (2048 rows)
__device__ __nv_bfloat16 d_dw_s [ (size_t)HDTOT * GK ];
__device__ __nv_bfloat16 d_y_s  [ (size_t)S_LEN * GK ];

__device__ __nv_bfloat16 d_qf   [ (size_t)S_LEN * NH * 256 ];     // [hi|lo]
__device__ __nv_bfloat16 d_kf   [ (size_t)S_LEN * NH * 256 ];     // [hi|lo]
__device__ __nv_bfloat16 d_v2   [ (size_t)S_LEN * NH * 256 ];     // [hi|lo]
__device__ __nv_bfloat16 d_kvs_f[ (size_t)NCH * NH * 128 * 256 ]; // [hi|lo]

__device__ float c_invfreq[64];
__device__ float c_slopes[16];

// ---------------------------------------------------------------------------
// PTX helpers (sm_80+ only)
// ---------------------------------------------------------------------------
__device__ __forceinline__ uint32_t smem_u32(const void* p) {
    uint32_t a;
    asm("{ .reg .u64 t; cvta.to.shared.u64 t, %1; cvt.u32.u64 %0, t; }" : "=r"(a) : "l"(p));
    return a;
}
__device__ __forceinline__ void cp_async16(uint32_t dst, const void* src) {
    asm volatile("cp.async.cg.shared.global [%0], [%1], 16;"
                 :: "r"(dst), "l"(__cvta_generic_to_global(src)) : "memory");
}
#define CP_COMMIT() asm volatile("cp.async.commit_group;" ::: "memory")
#define CP_WAIT0()  asm volatile("cp.async.wait_group 0;" ::: "memory")

__device__ __forceinline__ void ldsm_x4(uint32_t& r0, uint32_t& r1,
                                        uint32_t& r2, uint32_t& r3, uint32_t addr) {
    asm volatile("ldmatrix.sync.aligned.m8n8.x4.shared.b16 {%0,%1,%2,%3}, [%4];"
                 : "=r"(r0), "=r"(r1), "=r"(r2), "=r"(r3) : "r"(addr));
}
__device__ __forceinline__ void ldsm_x4_t(uint32_t& r0, uint32_t& r1,
                                          uint32_t& r2, uint32_t& r3, uint32_t addr) {
    asm volatile("ldmatrix.sync.aligned.m8n8.x4.trans.shared.b16 {%0,%1,%2,%3}, [%4];"
                 : "=r"(r0), "=r"(r1), "=r"(r2), "=r"(r3) : "r"(addr));
}
__device__ __forceinline__ void mma_bf16(float* d, uint32_t a0, uint32_t a1,
                                         uint32_t a2, uint32_t a3,
                                         uint32_t b0, uint32_t b1) {
    asm volatile("mma.sync.aligned.m16n8k16.row.col.f32.bf16.bf16.f32 "
                 "{%0,%1,%2,%3}, {%4,%5,%6,%7}, {%8,%9}, {%0,%1,%2,%3};"
                 : "+f"(d[0]), "+f"(d[1]), "+f"(d[2]), "+f"(d[3])
                 : "r"(a0), "r"(a1), "r"(a2), "r"(a3), "r"(b0), "r"(b1));
}

__device__ __forceinline__ void split_bf(float v, __nv_bfloat16& hi, __nv_bfloat16& lo) {
    hi = __float2bfloat16(v);
    lo = __float2bfloat16(v - __bfloat162float(hi));
}
__device__ __forceinline__ uint32_t pack_bf2(__nv_bfloat16 a, __nv_bfloat16 b) {
    __nv_bfloat162 t; t.x = a; t.y = b;
    return *(uint32_t*)&t;
}

#define SW128(o) ((o) ^ (((o) >> 3) & 0x70))

// ---------------------------------------------------------------------------
// Tables
// ---------------------------------------------------------------------------
__global__ void init_tables_kernel() {
    int t = threadIdx.x;
    if (t < 64) {
        double e = ((double)(2 * t) / 128.0) * log(600000.0);
        c_invfreq[t] = (float)exp(-e);
    }
    if (t < 16) {
        double s = exp2(-0.5 * (double)(t + 1));
        c_slopes[t] = (float)(s * (1.0 - 0.0 / 19.0 + 1e-5));
    }
}

// ---------------------------------------------------------------------------
// fp32 -> 3-plane split-bf16 (round-11 proven; linear streaming, no re-reads)
//  A pattern (isA=1): [hi | lo | hi]   B pattern: [hi | hi | lo]
// ---------------------------------------------------------------------------
__global__ __launch_bounds__(256)
void split_kernel(const float* __restrict__ src, __nv_bfloat16* __restrict__ dst, int isA)
{
    size_t idx = ((size_t)blockIdx.x * 256 + threadIdx.x) * 8;
    size_t r = idx >> 11;
    int    k = (int)(idx & 2047);

    float x[8];
    *(float4*)&x[0] = *(const float4*)&src[idx];
    *(float4*)&x[4] = *(const float4*)&src[idx + 4];

    __nv_bfloat16 hi[8], lo[8];
#pragma unroll
    for (int j = 0; j < 8; j++) split_bf(x[j], hi[j], lo[j]);
    __nv_bfloat16* base = dst + r * GK + k;
    *(uint4*)(base)        = *(uint4*)hi;
    *(uint4*)(base + 2048) = isA ? *(uint4*)lo : *(uint4*)hi;
    *(uint4*)(base + 4096) = isA ? *(uint4*)hi : *(uint4*)lo;
}

// ---------------------------------------------------------------------------
// HMMA GEMM: 128x128 tile, 256 thr (2x4 warps), BK=64, 3-stage, 2 CTA/SM.
// EPI=0: plain fp32 store.
// EPI=1: mega qkv+gate. tn 0-47: fused rmsnorm/rope/split epilogue regions
//        (0=q, 1=k, 2=v); tn 48-63: plain fp32 store to d_g.
// ---------------------------------------------------------------------------
__device__ __forceinline__ void g_load_stage(uint32_t sA,
                                             const __nv_bfloat16* ga,
                                             const __nv_bfloat16* gb, int k0)
{
    const int t = threadIdx.x;
#pragma unroll
    for (int i = 0; i < 4; i++) {
        int c   = t + i * 256;
        int row = c >> 3;
        int ch  = c & 7;
        uint32_t off = SW128(row * 128 + ch * 16);
        cp_async16(sA + off,         ga + (size_t)row * GK + k0 + ch * 8);
        cp_async16(sA + 16384 + off, gb + (size_t)row * GK + k0 + ch * 8);
    }
    CP_COMMIT();
}

template <int EPI>
__global__ __launch_bounds__(256, 2)
void hmma_gemm(const __nv_bfloat16* __restrict__ A, const __nv_bfloat16* __restrict__ B,
               const float* __restrict__ bias, float* __restrict__ C, int N,
               const int* __restrict__ positions,
               const float* __restrict__ qnw, const float* __restrict__ knw,
               float* __restrict__ Cg)
{
    extern __shared__ char smraw[];
    const uint32_t sbase = smem_u32(smraw);
    const int tid = threadIdx.x;
    const int wid = tid >> 5;
    const int lid = tid & 31;
    const int wm  = wid >> 2;
    const int wn  = wid & 3;

    const int Nt  = N >> 7;
    const int bid = blockIdx.x;
    const int g   = bid / (8 * Nt);
    const int rem = bid % (8 * Nt);
    const int tm  = g * 8 + (rem & 7);
    const int tn  = rem >> 3;

    const __nv_bfloat16* ga = A + (size_t)tm * 128 * GK;
    const __nv_bfloat16* gb = B + (size_t)tn * 128 * GK;

    float acc[4][4][4];
#pragma unroll
    for (int i = 0; i < 4; i++)
#pragma unroll
        for (int j = 0; j < 4; j++)
#pragma unroll
            for (int k = 0; k < 4; k++) acc[i][j][k] = 0.f;

#pragma unroll
    for (int s = 0; s < GSTG; s++)
        g_load_stage(sbase + s * STAGE_BYTES, ga, gb, s * BKG);

    const int arow = wm * 64 + (lid & 15);
    const int akb  = (lid >> 4) * 16;
    const int bg   = lid >> 3;
    const int brow = wn * 32 + ((bg >> 1) * 8) + (lid & 7);
    const int bkb  = (bg & 1) * 16;

    for (int it = 0; it < NSTEP; it++) {
        const int remi = NSTEP - 1 - it;
        if      (remi >= 2) asm volatile("cp.async.wait_group 2;" ::: "memory");
        else if (remi == 1) asm volatile("cp.async.wait_group 1;" ::: "memory");
        else                asm volatile("cp.async.wait_group 0;" ::: "memory");
        __syncthreads();

        const uint32_t sA = sbase + (it % GSTG) * STAGE_BYTES;
        const uint32_t sB = sA + 16384;

#pragma unroll
        for (int kk = 0; kk < BKG; kk += 16) {
            uint32_t a[4][4];
#pragma unroll
            for (int mt = 0; mt < 4; mt++) {
                uint32_t off = SW128((uint32_t)(arow + mt * 16) * 128 + kk * 2 + akb);
                ldsm_x4(a[mt][0], a[mt][1], a[mt][2], a[mt][3], sA + off);
            }
            uint32_t b[4][2];
#pragma unroll
            for (int bp = 0; bp < 2; bp++) {
                uint32_t off = SW128((uint32_t)(brow + bp * 16) * 128 + kk * 2 + bkb);
                uint32_t r0, r1, r2, r3;
                ldsm_x4(r0, r1, r2, r3, sB + off);
                b[bp * 2][0] = r0;     b[bp * 2][1] = r1;
                b[bp * 2 + 1][0] = r2; b[bp * 2 + 1][1] = r3;
            }
#pragma unroll
            for (int mt = 0; mt < 4; mt++)
#pragma unroll
                for (int nt = 0; nt < 4; nt++)
                    mma_bf16(acc[mt][nt], a[mt][0], a[mt][1], a[mt][2], a[mt][3],
                             b[nt][0], b[nt][1]);
        }

        __syncthreads();
        if (it + GSTG < NSTEP)
            g_load_stage(sA, ga, gb, (it + GSTG) * BKG);
    }

    const int r0 = lid >> 2;
    const int c0 = (lid & 3) * 2;

    if (EPI == 0) {
#pragma unroll
        for (int mt = 0; mt < 4; mt++) {
            int rowa = tm * 128 + wm * 64 + mt * 16 + r0;
#pragma unroll
            for (int nt = 0; nt < 4; nt++) {
                int col = tn * 128 + wn * 32 + nt * 8 + c0;
                float2 v0, v1;
                v0.x = acc[mt][nt][0]; v0.y = acc[mt][nt][1];
                v1.x = acc[mt][nt][2]; v1.y = acc[mt][nt][3];
                *(float2*)&C[(size_t)rowa * N + col]       = v0;
                *(float2*)&C[(size_t)(rowa + 8) * N + col] = v1;
            }
        }
    } else {
        const int region = tn >> 4;     // 0=q, 1=k, 2=v, 3=gate
        if (region == 3) {
            // gate tile: plain fp32 store to d_g
#pragma unroll
            for (int mt = 0; mt < 4; mt++) {
                int rowa = tm * 128 + wm * 64 + mt * 16 + r0;
#pragma unroll
                for (int nt = 0; nt < 4; nt++) {
                    int col = (tn - 48) * 128 + wn * 32 + nt * 8 + c0;
                    float2 v0, v1;
                    v0.x = acc[mt][nt][0]; v0.y = acc[mt][nt][1];
                    v1.x = acc[mt][nt][2]; v1.y = acc[mt][nt][3];
                    *(float2*)&Cg[(size_t)rowa * HDTOT + col]       = v0;
                    *(float2*)&Cg[(size_t)(rowa + 8) * HDTOT + col] = v1;
                }
            }
            return;
        }

        // ---- fused qkv epilogue (tile = 128 tokens x one head region) ----
        const int h  = tn & 15;
        const int s0 = tm * 128;
        float* T = (float*)smraw;       // [128][132]
        float* R = T + 128 * 132;       // rstd[128]

#pragma unroll
        for (int nt = 0; nt < 4; nt++) {
            int col = wn * 32 + nt * 8 + c0;
            float bx = __ldg(&bias[tn * 128 + col]);
            float by = __ldg(&bias[tn * 128 + col + 1]);
#pragma unroll
            for (int mt = 0; mt < 4; mt++) {
                int r = wm * 64 + mt * 16 + r0;
                float2 v0, v1;
                v0.x = acc[mt][nt][0] + bx; v0.y = acc[mt][nt][1] + by;
                v1.x = acc[mt][nt][2] + bx; v1.y = acc[mt][nt][3] + by;
                *(float2*)&T[r * 132 + col]       = v0;
                *(float2*)&T[(r + 8) * 132 + col] = v1;
            }
        }
        __syncthreads();

        if (region < 2) {
            {
                int row = tid >> 1, st = (tid & 1) * 64;
                float s = 0.f;
#pragma unroll
                for (int j = 0; j < 64; j += 4) {
                    float4 v = *(const float4*)&T[row * 132 + st + j];
                    s += v.x * v.x + v.y * v.y + v.z * v.z + v.w * v.w;
                }
                s += __shfl_xor_sync(0xffffffffu, s, 1);
                if ((tid & 1) == 0)
                    R[row] = rsqrtf(s * (1.f / 128.f) + EPS);
            }
            __syncthreads();

            {
                const float* w = (region == 0) ? qnw : knw;
                int row = tid >> 1, i0 = (tid & 1) * 32;
                float rs  = R[row];
                float pos = (float)positions[s0 + row];
#pragma unroll 4
                for (int i = i0; i < i0 + 32; i++) {
                    float x1 = T[row * 132 + i]      * rs * w[i];
                    float x2 = T[row * 132 + i + 64] * rs * w[i + 64];
                    float sn, cs2;
                    sincosf(pos * c_invfreq[i], &sn, &cs2);
                    float o1 = x1 * cs2 - x2 * sn;
                    float o2 = x2 * cs2 + x1 * sn;
                    if (region == 0) { o1 *= SCALE_Q; o2 *= SCALE_Q; }
                    T[row * 132 + i]      = o1;
                    T[row * 132 + i + 64] = o2;
                }
            }
            __syncthreads();

            __nv_bfloat16* dst = (region == 0) ? d_qf : d_kf;
#pragma unroll
            for (int l = 0; l < 16; l++) {
                int ci = tid + l * 256;
                int row = ci >> 5, c16 = ci & 31;
                int plane = c16 >> 4, within = c16 & 15;
                float x[8];
                *(float4*)&x[0] = *(const float4*)&T[row * 132 + within * 8];
                *(float4*)&x[4] = *(const float4*)&T[row * 132 + within * 8 + 4];
                __nv_bfloat16 h8[8], l8[8];
#pragma unroll
                for (int q = 0; q < 8; q++) split_bf(x[q], h8[q], l8[q]);
                uint4 outv = plane ? *(uint4*)l8 : *(uint4*)h8;
                *(uint4*)(dst + ((size_t)(s0 + row) * NH + h) * 256 + c16 * 8) = outv;
            }
        } else {
#pragma unroll
            for (int l = 0; l < 16; l++) {
                int ci = tid + l * 256;
                int row = ci >> 5, c16 = ci & 31;
                int plane = c16 >> 4, within = c16 & 15;
                float x[8];
                *(float4*)&x[0] = *(const float4*)&T[row * 132 + within * 8];
                *(float4*)&x[4] = *(const float4*)&T[row * 132 + within * 8 + 4];
                __nv_bfloat16 h8[8], l8[8];
#pragma unroll
                for (int q = 0; q < 8; q++) split_bf(x[q], h8[q], l8[q]);
                uint4 outv = plane ? *(uint4*)l8 : *(uint4*)h8;
                *(uint4*)(d_v2 + ((size_t)(s0 + row) * NH + h) * 256 + c16 * 8) = outv;
            }
        }
    }
}

// ---------------------------------------------------------------------------
// Phase 1 (HMMA): per-64-chunk KV^T, 2-plane smem.
// ---------------------------------------------------------------------------
__global__ __launch_bounds__(256, 2)
void chunk_kv_hmma()
{
    extern __shared__ char sm[];
    const uint32_t sb = smem_u32(sm);
    const int tid = threadIdx.x;
    const int wid = tid >> 5, lid = tid & 31;
    const int wm = wid >> 2, wn = wid & 3;
    const int ch = blockIdx.x, h = blockIdx.y;
    const float slope = c_slopes[h];
    const int t0 = ch * CHK;

    float acc[4][4][4];
#pragma unroll
    for (int i = 0; i < 4; i++)
#pragma unroll
        for (int j = 0; j < 4; j++)
#pragma unroll
            for (int k = 0; k < 4; k++) acc[i][j][k] = 0.f;

#pragma unroll
    for (int l = 0; l < 4; l++) {
        int ci = tid + l * 256;
        int j  = ci >> 4;
        int c8 = ci & 15;
        const __nv_bfloat16* kfrow = d_kf + ((size_t)(t0 + j) * NH + h) * 256;
        uint4 uh = *(const uint4*)(kfrow + c8 * 8);
        uint4 ul = *(const uint4*)(kfrow + 128 + c8 * 8);
        const __nv_bfloat16* ah = (const __nv_bfloat16*)&uh;
        const __nv_bfloat16* al = (const __nv_bfloat16*)&ul;
        float kd = expf(-slope * (float)(CHK - 1 - j));
        __nv_bfloat16 oh[8], ol[8];
#pragma unroll
        for (int q = 0; q < 8; q++) {
            float t = (__bfloat162float(ah[q]) + __bfloat162float(al[q])) * kd;
            split_bf(t, oh[q], ol[q]);
        }
        char* kb = sm + C2_K + c8 * 16;
        *(uint4*)(kb + (size_t)j * 272)        = *(uint4*)oh;
        *(uint4*)(kb + (size_t)(j + 64) * 272) = *(uint4*)ol;
        const __nv_bfloat16* vrow = d_v2 + ((size_t)(t0 + j) * NH + h) * 256;
        uint4 vh = *(const uint4*)(vrow + c8 * 8);
        uint4 vl = *(const uint4*)(vrow + 128 + c8 * 8);
        char* vb = sm + C2_V + c8 * 16;
        *(uint4*)(vb + (size_t)j * 272)        = vh;
        *(uint4*)(vb + (size_t)(j + 64) * 272) = vl;
    }
    __syncthreads();

#pragma unroll
    for (int ks = 0; ks < 192; ks += 16) {
        const int var = (ks < 128) ? ks : ks - 128;   // v [hi|lo|hi]
        const int kbr = (ks < 64) ? ks : ks - 64;     // k [hi|hi|lo]
        uint32_t a[4][4];
#pragma unroll
        for (int mt = 0; mt < 4; mt++) {
            int e0 = wm * 64 + mt * 16;
            uint32_t addr = sb + C2_V +
                (uint32_t)(var + (lid >> 4) * 8 + (lid & 7)) * 272 +
                e0 * 2 + ((lid >> 3) & 1) * 16;
            ldsm_x4_t(a[mt][0], a[mt][1], a[mt][2], a[mt][3], addr);
        }
        uint32_t b[4][2];
#pragma unroll
        for (int nb = 0; nb < 2; nb++) {
            int d0 = wn * 32 + nb * 16;
            uint32_t addr = sb + C2_K +
                (uint32_t)(kbr + ((lid >> 3) & 1) * 8 + (lid & 7)) * 272 +
                d0 * 2 + (lid >> 4) * 16;
            uint32_t r0, r1, r2, r3;
            ldsm_x4_t(r0, r1, r2, r3, addr);
            b[nb * 2][0] = r0;     b[nb * 2][1] = r1;
            b[nb * 2 + 1][0] = r2; b[nb * 2 + 1][1] = r3;
        }
#pragma unroll
        for (int mt = 0; mt < 4; mt++)
#pragma unroll
            for (int nt = 0; nt < 4; nt++)
                mma_bf16(acc[mt][nt], a[mt][0], a[mt][1], a[mt][2], a[mt][3],
                         b[nt][0], b[nt][1]);
    }

    size_t base = ((size_t)(ch * NH + h)) * HD * HD;
#pragma unroll
    for (int mt = 0; mt < 4; mt++) {
        int e = wm * 64 + mt * 16 + (lid >> 2);
#pragma unroll
        for (int nt = 0; nt < 4; nt++) {
            int dd = wn * 32 + nt * 8 + (lid & 3) * 2;
            float2 v0, v1;
            v0.x = acc[mt][nt][0]; v0.y = acc[mt][nt][1];
            v1.x = acc[mt][nt][2]; v1.y = acc[mt][nt][3];
            *(float2*)&d_kvc[base + (size_t)e * HD + dd]       = v0;
            *(float2*)&d_kvc[base + (size_t)(e + 8) * HD + dd] = v1;
        }
    }
}

// ---------------------------------------------------------------------------
// Phase 1b: scan over 128 chunks, emit 2-plane bf16 prefix states.
// ---------------------------------------------------------------------------
__global__ __launch_bounds__(256)
void kv_scan_kernel()
{
    int p  = blockIdx.x * 256 + threadIdx.x;
    int h  = p >> 12;
    int e  = (p >> 5) & 127;
    int d4 = (p & 31) * 4;
    float bd = expf(-c_slopes[h] * (float)CHK);
    float4 st = make_float4(0.f, 0.f, 0.f, 0.f);
#pragma unroll 1
    for (int c = 0; c < NCH; c++) {
        size_t ro = ((size_t)(c * NH + h) * 128 + e);
        __nv_bfloat16 h0, l0, h1, l1, h2, l2, h3, l3;
        split_bf(st.x, h0, l0); split_bf(st.y, h1, l1);
        split_bf(st.z, h2, l2); split_bf(st.w, h3, l3);
        uint2 hp, lp;
        hp.x = pack_bf2(h0, h1); hp.y = pack_bf2(h2, h3);
        lp.x = pack_bf2(l0, l1); lp.y = pack_bf2(l2, l3);
        __nv_bfloat16* orow = d_kvs_f + ro * 256;
        *(uint2*)(orow + d4)       = hp;
        *(uint2*)(orow + 128 + d4) = lp;
        float4 v = *(const float4*)(d_kvc + ro * 128 + d4);
        st.x = bd * st.x + v.x; st.y = bd * st.y + v.y;
        st.z = bd * st.z + v.z; st.w = bd * st.w + v.w;
    }
}

// ---------------------------------------------------------------------------
// Phase 2 (HMMA): inter + diagonal intra; single prefetch phase, 2-plane smem.
// ---------------------------------------------------------------------------
__global__ __launch_bounds__(256, 1)
void attn_hmma_kernel()
{
    extern __shared__ char sm[];
    const uint32_t sb = smem_u32(sm);
    const int tid = threadIdx.x;
    const int wid = tid >> 5, lid = tid & 31;
    const int wm = wid >> 2, wn = wid & 3;
    const int ch = blockIdx.x, h = blockIdx.y;
    const float slope = c_slopes[h];
    const int s0 = ch * CHK;

    float* tbl = (float*)(sm + A2_TBL);
    if (tid < 65) tbl[tid] = expf(-slope * (float)tid);

    // ---- single prefetch phase: q, state, k, v ----
#pragma unroll
    for (int l = 0; l < 8; l++) {
        int ci = tid + l * 256;
        int r = ci >> 5, c16 = ci & 31;
        cp_async16(sb + A2_SQ + r * Q2_ROW + c16 * 16,
                   d_qf + ((size_t)(s0 + r) * NH + h) * 256 + c16 * 8);
    }
    {
        const __nv_bfloat16* kvb = d_kvs_f + ((size_t)(ch * NH + h)) * 128 * 256;
#pragma unroll
        for (int l = 0; l < 16; l++) {
            int ci = tid + l * 256;
            int r = ci >> 5, c16 = ci & 31;
            cp_async16(sb + A2_SS + r * Q2_ROW + c16 * 16,
                       kvb + (size_t)r * 256 + c16 * 8);
        }
    }
#pragma unroll
    for (int l = 0; l < 8; l++) {
        int ci = tid + l * 256;
        int r = ci >> 5, c16 = ci & 31;
        cp_async16(sb + A2_SK + r * Q2_ROW + c16 * 16,
                   d_kf + ((size_t)(s0 + r) * NH + h) * 256 + c16 * 8);
    }
#pragma unroll
    for (int l = 0; l < 8; l++) {
        int ci = tid + l * 256;
        int r = ci >> 5, c16 = ci & 31;
        int plane = c16 >> 4, within = c16 & 15;
        cp_async16(sb + A2_SV + (r + plane * 64) * V2_ROW + within * 16,
                   d_v2 + ((size_t)(s0 + r) * NH + h) * 256 + c16 * 8);
    }
    CP_COMMIT();
    CP_WAIT0();
    __syncthreads();

    // ---- INTER ----
    float acc[2][4][4];
#pragma unroll
    for (int i = 0; i < 2; i++)
#pragma unroll
        for (int j = 0; j < 4; j++)
#pragma unroll
            for (int k = 0; k < 4; k++) acc[i][j][k] = 0.f;

    const int bg = lid >> 3;
#pragma unroll
    for (int ks = 0; ks < 384; ks += 16) {
        const int aks = (ks < 256) ? ks : ks - 256;
        const int bks = (ks < 256) ? (ks & 127) : (ks - 128);
        uint32_t a[2][4];
#pragma unroll
        for (int mt = 0; mt < 2; mt++) {
            uint32_t addr = sb + A2_SQ +
                (uint32_t)(wm * 32 + mt * 16 + (lid & 15)) * Q2_ROW +
                aks * 2 + (lid >> 4) * 16;
            ldsm_x4(a[mt][0], a[mt][1], a[mt][2], a[mt][3], addr);
        }
        uint32_t b[4][2];
#pragma unroll
        for (int nb = 0; nb < 2; nb++) {
            int n0 = wn * 32 + nb * 16;
            uint32_t addr = sb + A2_SS +
                (uint32_t)(n0 + (bg >> 1) * 8 + (lid & 7)) * Q2_ROW +
                bks * 2 + (bg & 1) * 16;
            uint32_t r0, r1, r2, r3;
            ldsm_x4(r0, r1, r2, r3, addr);
            b[nb * 2][0] = r0;     b[nb * 2][1] = r1;
            b[nb * 2 + 1][0] = r2; b[nb * 2 + 1][1] = r3;
        }
#pragma unroll
        for (int mt = 0; mt < 2; mt++)
#pragma unroll
            for (int nt = 0; nt < 4; nt++)
                mma_bf16(acc[mt][nt], a[mt][0], a[mt][1], a[mt][2], a[mt][3],
                         b[nt][0], b[nt][1]);
    }
#pragma unroll
    for (int mt = 0; mt < 2; mt++) {
        int r = wm * 32 + mt * 16 + (lid >> 2);
        float q0 = tbl[r + 1];
        float q1 = tbl[r + 9];
#pragma unroll
        for (int nt = 0; nt < 4; nt++) {
            acc[mt][nt][0] *= q0; acc[mt][nt][1] *= q0;
            acc[mt][nt][2] *= q1; acc[mt][nt][3] *= q1;
        }
    }

    // ---- scores ----
    float accS[2][2][4];
#pragma unroll
    for (int i = 0; i < 2; i++)
#pragma unroll
        for (int j = 0; j < 2; j++)
#pragma unroll
            for (int k = 0; k < 4; k++) accS[i][j][k] = 0.f;

#pragma unroll
    for (int ks = 0; ks < 384; ks += 16) {
        const int aks = (ks < 256) ? ks : ks - 256;
        const int bks = (ks < 256) ? (ks & 127) : (ks - 128);
        uint32_t a[2][4];
#pragma unroll
        for (int mt = 0; mt < 2; mt++) {
            uint32_t addr = sb + A2_SQ +
                (uint32_t)(wm * 32 + mt * 16 + (lid & 15)) * Q2_ROW +
                aks * 2 + (lid >> 4) * 16;
            ldsm_x4(a[mt][0], a[mt][1], a[mt][2], a[mt][3], addr);
        }
        int n0 = wn * 16;
        uint32_t addr = sb + A2_SK +
            (uint32_t)(n0 + (bg >> 1) * 8 + (lid & 7)) * Q2_ROW +
            bks * 2 + (bg & 1) * 16;
        uint32_t b0, b1, b2, b3;
        ldsm_x4(b0, b1, b2, b3, addr);
#pragma unroll
        for (int mt = 0; mt < 2; mt++) {
            mma_bf16(accS[mt][0], a[mt][0], a[mt][1], a[mt][2], a[mt][3], b0, b1);
            mma_bf16(accS[mt][1], a[mt][0], a[mt][1], a[mt][2], a[mt][3], b2, b3);
        }
    }

    // ---- mask + decay + 2-plane P fold ----
#pragma unroll
    for (int mt = 0; mt < 2; mt++) {
        int r = wm * 32 + mt * 16 + (lid >> 2);
#pragma unroll
        for (int nt = 0; nt < 2; nt++) {
            int cc = wn * 16 + nt * 8 + (lid & 3) * 2;
            int d00 = r - cc;
            float v00 = (d00 >= 0) ? accS[mt][nt][0] * tbl[d00]     : 0.f;
            float v01 = (d00 >= 1) ? accS[mt][nt][1] * tbl[d00 - 1] : 0.f;
            int d10 = d00 + 8;
            float v10 = (d10 >= 0) ? accS[mt][nt][2] * tbl[d10]     : 0.f;
            float v11 = (d10 >= 1) ? accS[mt][nt][3] * tbl[d10 - 1] : 0.f;
            __nv_bfloat16 h00, l00, h01, l01, h10, l10, h11, l11;
            split_bf(v00, h00, l00); split_bf(v01, h01, l01);
            split_bf(v10, h10, l10); split_bf(v11, h11, l11);
            char* b0p = sm + A2_SP + r * Q2_ROW + cc * 2;
            *(uint32_t*)(b0p)       = pack_bf2(h00, h01);
            *(uint32_t*)(b0p + 128) = pack_bf2(l00, l01);
            char* b1p = b0p + 8 * Q2_ROW;
            *(uint32_t*)(b1p)       = pack_bf2(h10, h11);
            *(uint32_t*)(b1p + 128) = pack_bf2(l10, l11);
        }
    }
    __syncthreads();

    // ---- PV ----
#pragma unroll
    for (int ks = 0; ks < 192; ks += 16) {
        const int aks = (ks < 128) ? ks : ks - 128;
        const int vbr = (ks < 64) ? ks : ks - 64;
        uint32_t a[2][4];
#pragma unroll
        for (int mt = 0; mt < 2; mt++) {
            uint32_t addr = sb + A2_SP +
                (uint32_t)(wm * 32 + mt * 16 + (lid & 15)) * Q2_ROW +
                aks * 2 + (lid >> 4) * 16;
            ldsm_x4(a[mt][0], a[mt][1], a[mt][2], a[mt][3], addr);
        }
        uint32_t b[4][2];
#pragma unroll
        for (int nb = 0; nb < 2; nb++) {
            int e0 = wn * 32 + nb * 16;
            uint32_t addr = sb + A2_SV +
                (uint32_t)(vbr + ((lid >> 3) & 1) * 8 + (lid & 7)) * V2_ROW +
                e0 * 2 + (lid >> 4) * 16;
            uint32_t r0, r1, r2, r3;
            ldsm_x4_t(r0, r1, r2, r3, addr);
            b[nb * 2][0] = r0;     b[nb * 2][1] = r1;
            b[nb * 2 + 1][0] = r2; b[nb * 2 + 1][1] = r3;
        }
#pragma unroll
        for (int mt = 0; mt < 2; mt++)
#pragma unroll
            for (int nt = 0; nt < 4; nt++)
                mma_bf16(acc[mt][nt], a[mt][0], a[mt][1], a[mt][2], a[mt][3],
                         b[nt][0], b[nt][1]);
    }

    // store O
#pragma unroll
    for (int mt = 0; mt < 2; mt++) {
        int r = wm * 32 + mt * 16 + (lid >> 2);
#pragma unroll
        for (int nt = 0; nt < 4; nt++) {
            int col = wn * 32 + nt * 8 + (lid & 3) * 2;
            float2 v0, v1;
            v0.x = acc[mt][nt][0]; v0.y = acc[mt][nt][1];
            v1.x = acc[mt][nt][2]; v1.y = acc[mt][nt][3];
            *(float2*)&d_attn[(size_t)(s0 + r) * HDTOT + h * HD + col]     = v0;
            *(float2*)&d_attn[(size_t)(s0 + r + 8) * HDTOT + h * HD + col] = v1;
        }
    }
}

// ---------------------------------------------------------------------------
// Group-RMSNorm + sigmoid gating -> 3-plane split-bf16 y (A pattern)
// ---------------------------------------------------------------------------
__global__ __launch_bounds__(256)
void gate_kernel(const float* __restrict__ gnw)
{
    int s = blockIdx.x;
    int t = threadIdx.x;
    size_t base = (size_t)s * HDTOT + t * 8;

    float a[8];
    *(float4*)&a[0] = *(const float4*)&d_attn[base];
    *(float4*)&a[4] = *(const float4*)&d_attn[base + 4];

    float ss = 0.f;
#pragma unroll
    for (int j = 0; j < 8; j++) ss += a[j] * a[j];
#pragma unroll
    for (int off = 16; off > 0; off >>= 1)
        ss += __shfl_xor_sync(0xffffffffu, ss, off);
    float rstd = rsqrtf(ss * (1.f / 256.f) + EPS);

    float gv[8];
    *(float4*)&gv[0] = *(const float4*)&d_g[base];
    *(float4*)&gv[4] = *(const float4*)&d_g[base + 4];

    __nv_bfloat16 hi[8], lo[8];
#pragma unroll
    for (int j = 0; j < 8; j++) {
        float sig = 1.f / (1.f + expf(-gv[j]));
        float y = a[j] * rstd * gnw[t * 8 + j] * sig;
        split_bf(y, hi[j], lo[j]);
    }
    __nv_bfloat16* dst = d_y_s + (size_t)s * GK + t * 8;
    *(uint4*)(dst)        = *(uint4*)hi;
    *(uint4*)(dst + 2048) = *(uint4*)lo;
    *(uint4*)(dst + 4096) = *(uint4*)hi;
}

// ---------------------------------------------------------------------------
// Launch — single stream; qkv and gate GEMMs merged into one launch.
// ---------------------------------------------------------------------------
extern "C" void kernel_launch(void* const* d_in, const int* in_sizes, int n_in,
                              void* d_out, int out_size)
{
    const float* hs     = (const float*)d_in[0];
    const int*   pos    = (const int*)  d_in[1];
    const float* qkv_w  = (const float*)d_in[2];
    const float* qkv_b  = (const float*)d_in[3];
    const float* qnw    = (const float*)d_in[4];
    const float* knw    = (const float*)d_in[5];
    const float* g_w    = (const float*)d_in[6];
    const float* gnw    = (const float*)d_in[7];
    const float* dens_w = (const float*)d_in[8];
    float* out = (float*)d_out;

    float *p_g;
    __nv_bfloat16 *p_hs_s, *p_bw_s, *p_dw_s, *p_y_s;
    cudaGetSymbolAddress((void**)&p_g,    d_g);
    cudaGetSymbolAddress((void**)&p_hs_s, d_hs_s);
    cudaGetSymbolAddress((void**)&p_bw_s, d_bw_s);
    cudaGetSymbolAddress((void**)&p_dw_s, d_dw_s);
    cudaGetSymbolAddress((void**)&p_y_s,  d_y_s);

    cudaFuncSetAttribute(hmma_gemm<0>,
                         cudaFuncAttributeMaxDynamicSharedMemorySize, GEMM_SMEM);
    cudaFuncSetAttribute(hmma_gemm<1>,
                         cudaFuncAttributeMaxDynamicSharedMemorySize, GEMM_SMEM);
    cudaFuncSetAttribute(attn_hmma_kernel,
                         cudaFuncAttributeMaxDynamicSharedMemorySize, ATTN_SMEM);
    cudaFuncSetAttribute(chunk_kv_hmma,
                         cudaFuncAttributeMaxDynamicSharedMemorySize, CHUNK_SMEM);

    init_tables_kernel<<<1, 64>>>();

    // splits: A operand, B = [qkv_w rows | g_w rows], dense weights
    split_kernel<<<(S_LEN * HID) / (256 * 8), 256>>>(hs, p_hs_s, 1);
    split_kernel<<<(QKV_N * HID) / (256 * 8), 256>>>(qkv_w, p_bw_s, 0);
    split_kernel<<<(HDTOT * HID) / (256 * 8), 256>>>(g_w, p_bw_s + (size_t)QKV_N * GK, 0);
    split_kernel<<<(HDTOT * HID) / (256 * 8), 256>>>(dens_w, p_dw_s, 0);

    // mega GEMM: qkv (fused epilogue) + gate (plain store) in one launch
    hmma_gemm<1><<<(S_LEN / 128) * (MEGA_N / 128), 256, GEMM_SMEM>>>(
        p_hs_s, p_bw_s, qkv_b, nullptr, MEGA_N, pos, qnw, knw, p_g);

    chunk_kv_hmma<<<dim3(NCH, NH), 256, CHUNK_SMEM>>>();
    kv_scan_kernel<<<256, 256>>>();
    attn_hmma_kernel<<<dim3(NCH, NH), 256, ATTN_SMEM>>>();

    gate_kernel<<<S_LEN, 256>>>(gnw);

    hmma_gemm<0><<<(S_LEN / 128) * (HDTOT / 128), 256, GEMM_SMEM>>>(
        p_y_s, p_dw_s, nullptr, out, HDTOT, nullptr, nullptr, nullptr, nullptr);
}

// round 15
// speedup vs baseline: 1.0429x; 1.0429x over previous
#include <cuda_runtime.h>
#include <cuda_bf16.h>
#include <math.h>
#include <stdint.h>

// ---------------------------------------------------------------------------
// Problem constants
// ---------------------------------------------------------------------------
#define S_LEN   8192
#define HID     2048
#define NH      16
#define HD      128
#define CHK     64
#define NCH     128           // S / CHK
#define HDTOT   2048
#define QKV_N   6144
#define EPS     1e-5f
#define SCALE_Q 0.08838834764831845f

// split-K GEMM constants (round-11 proven: 3-plane storage, 128x128, 3-stage)
#define GK      6144
#define BKG     64
#define NSTEP   96
#define GSTG    3
#define STAGE_BYTES (128*BKG*2 + 128*BKG*2)   // 32768
#define GEMM_SMEM   (GSTG * STAGE_BYTES)      // 98304

// attention smem: 2-plane operands, no aliasing, single load phase
#define Q2_ROW 528            // 256 bf16 + 16B pad
#define V2_ROW 272            // 128 bf16 + 16B pad
#define A2_SQ  0
#define A2_SS  33792          // q 64*528
#define A2_SK  (A2_SS + 128*528)   // 101376
#define A2_SV  (A2_SK + 64*528)    // 135168
#define A2_SP  (A2_SV + 128*272)   // 169984
#define A2_TBL (A2_SP + 64*528)    // 203776
#define ATTN_SMEM (A2_TBL + 288)   // 204064

// chunk_kv smem (2-plane)
#define C2_K 0
#define C2_V 34816            // 128*272
#define CHUNK_SMEM 69632

// ---------------------------------------------------------------------------
// Scratch (static device globals; no allocation allowed)
// ---------------------------------------------------------------------------
__device__ float d_attn[ (size_t)S_LEN * HDTOT ];
__device__ float d_g   [ (size_t)S_LEN * HDTOT ];
__device__ float d_kvc [ (size_t)NCH * NH * HD * HD ];

__device__ __nv_bfloat16 d_hs_s  [ (size_t)S_LEN * GK ];
__device__ __nv_bfloat16 d_qkvw_s[ (size_t)QKV_N * GK ];
__device__ __nv_bfloat16 d_gw_s  [ (size_t)HDTOT * GK ];
__device__ __nv_bfloat16 d_dw_s  [ (size_t)HDTOT * GK ];
__device__ __nv_bfloat16 d_y_s   [ (size_t)S_LEN * GK ];

__device__ __nv_bfloat16 d_qf   [ (size_t)S_LEN * NH * 256 ];     // [hi|lo]
__device__ __nv_bfloat16 d_kf   [ (size_t)S_LEN * NH * 256 ];     // [hi|lo]
__device__ __nv_bfloat16 d_v2   [ (size_t)S_LEN * NH * 256 ];     // [hi|lo]
__device__ __nv_bfloat16 d_kvs_f[ (size_t)NCH * NH * 128 * 256 ]; // [hi|lo]

__device__ float c_invfreq[64];
__device__ float c_slopes[16];

// ---------------------------------------------------------------------------
// PTX helpers (sm_80+ only)
// ---------------------------------------------------------------------------
__device__ __forceinline__ uint32_t smem_u32(const void* p) {
    uint32_t a;
    asm("{ .reg .u64 t; cvta.to.shared.u64 t, %1; cvt.u32.u64 %0, t; }" : "=r"(a) : "l"(p));
    return a;
}
__device__ __forceinline__ void cp_async16(uint32_t dst, const void* src) {
    asm volatile("cp.async.cg.shared.global [%0], [%1], 16;"
                 :: "r"(dst), "l"(__cvta_generic_to_global(src)) : "memory");
}
#define CP_COMMIT() asm volatile("cp.async.commit_group;" ::: "memory")
#define CP_WAIT0()  asm volatile("cp.async.wait_group 0;" ::: "memory")

__device__ __forceinline__ void ldsm_x4(uint32_t& r0, uint32_t& r1,
                                        uint32_t& r2, uint32_t& r3, uint32_t addr) {
    asm volatile("ldmatrix.sync.aligned.m8n8.x4.shared.b16 {%0,%1,%2,%3}, [%4];"
                 : "=r"(r0), "=r"(r1), "=r"(r2), "=r"(r3) : "r"(addr));
}
__device__ __forceinline__ void ldsm_x4_t(uint32_t& r0, uint32_t& r1,
                                          uint32_t& r2, uint32_t& r3, uint32_t addr) {
    asm volatile("ldmatrix.sync.aligned.m8n8.x4.trans.shared.b16 {%0,%1,%2,%3}, [%4];"
                 : "=r"(r0), "=r"(r1), "=r"(r2), "=r"(r3) : "r"(addr));
}
__device__ __forceinline__ void mma_bf16(float* d, uint32_t a0, uint32_t a1,
                                         uint32_t a2, uint32_t a3,
                                         uint32_t b0, uint32_t b1) {
    asm volatile("mma.sync.aligned.m16n8k16.row.col.f32.bf16.bf16.f32 "
                 "{%0,%1,%2,%3}, {%4,%5,%6,%7}, {%8,%9}, {%0,%1,%2,%3};"
                 : "+f"(d[0]), "+f"(d[1]), "+f"(d[2]), "+f"(d[3])
                 : "r"(a0), "r"(a1), "r"(a2), "r"(a3), "r"(b0), "r"(b1));
}

__device__ __forceinline__ void split_bf(float v, __nv_bfloat16& hi, __nv_bfloat16& lo) {
    hi = __float2bfloat16(v);
    lo = __float2bfloat16(v - __bfloat162float(hi));
}
__device__ __forceinline__ uint32_t pack_bf2(__nv_bfloat16 a, __nv_bfloat16 b) {
    __nv_bfloat162 t; t.x = a; t.y = b;
    return *(uint32_t*)&t;
}

#define SW128(o) ((o) ^ (((o) >> 3) & 0x70))

// ---------------------------------------------------------------------------
// Tables
// ---------------------------------------------------------------------------
__global__ void init_tables_kernel() {
    int t = threadIdx.x;
    if (t < 64) {
        double e = ((double)(2 * t) / 128.0) * log(600000.0);
        c_invfreq[t] = (float)exp(-e);
    }
    if (t < 16) {
        double s = exp2(-0.5 * (double)(t + 1));
        c_slopes[t] = (float)(s * (1.0 - 0.0 / 19.0 + 1e-5));
    }
}

// ---------------------------------------------------------------------------
// fp32 -> 3-plane split-bf16 (linear streaming; round-11 proven)
//  A pattern (isA=1): [hi | lo | hi]   B pattern: [hi | hi | lo]
// ---------------------------------------------------------------------------
__global__ __launch_bounds__(256)
void split_kernel(const float* __restrict__ src, __nv_bfloat16* __restrict__ dst, int isA)
{
    size_t idx = ((size_t)blockIdx.x * 256 + threadIdx.x) * 8;
    size_t r = idx >> 11;
    int    k = (int)(idx & 2047);

    float x[8];
    *(float4*)&x[0] = *(const float4*)&src[idx];
    *(float4*)&x[4] = *(const float4*)&src[idx + 4];

    __nv_bfloat16 hi[8], lo[8];
#pragma unroll
    for (int j = 0; j < 8; j++) split_bf(x[j], hi[j], lo[j]);
    __nv_bfloat16* base = dst + r * GK + k;
    *(uint4*)(base)        = *(uint4*)hi;
    *(uint4*)(base + 2048) = isA ? *(uint4*)lo : *(uint4*)hi;
    *(uint4*)(base + 4096) = isA ? *(uint4*)hi : *(uint4*)lo;
}

// ---------------------------------------------------------------------------
// HMMA GEMM: 128x128 tile, 256 thr (2x4 warps), BK=64, 3-stage, 2 CTA/SM.
// EPI=0: plain fp32 store.  EPI=1: fused qkv epilogue -> d_qf/d_kf/d_v2.
// ---------------------------------------------------------------------------
__device__ __forceinline__ void g_load_stage(uint32_t sA,
                                             const __nv_bfloat16* ga,
                                             const __nv_bfloat16* gb, int k0)
{
    const int t = threadIdx.x;
#pragma unroll
    for (int i = 0; i < 4; i++) {
        int c   = t + i * 256;
        int row = c >> 3;
        int ch  = c & 7;
        uint32_t off = SW128(row * 128 + ch * 16);
        cp_async16(sA + off,         ga + (size_t)row * GK + k0 + ch * 8);
        cp_async16(sA + 16384 + off, gb + (size_t)row * GK + k0 + ch * 8);
    }
    CP_COMMIT();
}

template <int EPI>
__global__ __launch_bounds__(256, 2)
void hmma_gemm(const __nv_bfloat16* __restrict__ A, const __nv_bfloat16* __restrict__ B,
               const float* __restrict__ bias, float* __restrict__ C, int N,
               const int* __restrict__ positions,
               const float* __restrict__ qnw, const float* __restrict__ knw)
{
    extern __shared__ char smraw[];
    const uint32_t sbase = smem_u32(smraw);
    const int tid = threadIdx.x;
    const int wid = tid >> 5;
    const int lid = tid & 31;
    const int wm  = wid >> 2;
    const int wn  = wid & 3;

    const int Nt  = N >> 7;
    const int bid = blockIdx.x;
    const int g   = bid / (8 * Nt);
    const int rem = bid % (8 * Nt);
    const int tm  = g * 8 + (rem & 7);
    const int tn  = rem >> 3;

    const __nv_bfloat16* ga = A + (size_t)tm * 128 * GK;
    const __nv_bfloat16* gb = B + (size_t)tn * 128 * GK;

    float acc[4][4][4];
#pragma unroll
    for (int i = 0; i < 4; i++)
#pragma unroll
        for (int j = 0; j < 4; j++)
#pragma unroll
            for (int k = 0; k < 4; k++) acc[i][j][k] = 0.f;

#pragma unroll
    for (int s = 0; s < GSTG; s++)
        g_load_stage(sbase + s * STAGE_BYTES, ga, gb, s * BKG);

    const int arow = wm * 64 + (lid & 15);
    const int akb  = (lid >> 4) * 16;
    const int bg   = lid >> 3;
    const int brow = wn * 32 + ((bg >> 1) * 8) + (lid & 7);
    const int bkb  = (bg & 1) * 16;

    for (int it = 0; it < NSTEP; it++) {
        const int remi = NSTEP - 1 - it;
        if      (remi >= 2) asm volatile("cp.async.wait_group 2;" ::: "memory");
        else if (remi == 1) asm volatile("cp.async.wait_group 1;" ::: "memory");
        else                asm volatile("cp.async.wait_group 0;" ::: "memory");
        __syncthreads();

        const uint32_t sA = sbase + (it % GSTG) * STAGE_BYTES;
        const uint32_t sB = sA + 16384;

#pragma unroll
        for (int kk = 0; kk < BKG; kk += 16) {
            uint32_t a[4][4];
#pragma unroll
            for (int mt = 0; mt < 4; mt++) {
                uint32_t off = SW128((uint32_t)(arow + mt * 16) * 128 + kk * 2 + akb);
                ldsm_x4(a[mt][0], a[mt][1], a[mt][2], a[mt][3], sA + off);
            }
            uint32_t b[4][2];
#pragma unroll
            for (int bp = 0; bp < 2; bp++) {
                uint32_t off = SW128((uint32_t)(brow + bp * 16) * 128 + kk * 2 + bkb);
                uint32_t r0, r1, r2, r3;
                ldsm_x4(r0, r1, r2, r3, sB + off);
                b[bp * 2][0] = r0;     b[bp * 2][1] = r1;
                b[bp * 2 + 1][0] = r2; b[bp * 2 + 1][1] = r3;
            }
#pragma unroll
            for (int mt = 0; mt < 4; mt++)
#pragma unroll
                for (int nt = 0; nt < 4; nt++)
                    mma_bf16(acc[mt][nt], a[mt][0], a[mt][1], a[mt][2], a[mt][3],
                             b[nt][0], b[nt][1]);
        }

        __syncthreads();
        if (it + GSTG < NSTEP)
            g_load_stage(sA, ga, gb, (it + GSTG) * BKG);
    }

    const int r0 = lid >> 2;
    const int c0 = (lid & 3) * 2;

    if (EPI == 0) {
#pragma unroll
        for (int mt = 0; mt < 4; mt++) {
            int rowa = tm * 128 + wm * 64 + mt * 16 + r0;
#pragma unroll
            for (int nt = 0; nt < 4; nt++) {
                int col = tn * 128 + wn * 32 + nt * 8 + c0;
                float2 v0, v1;
                v0.x = acc[mt][nt][0]; v0.y = acc[mt][nt][1];
                v1.x = acc[mt][nt][2]; v1.y = acc[mt][nt][3];
                *(float2*)&C[(size_t)rowa * N + col]       = v0;
                *(float2*)&C[(size_t)(rowa + 8) * N + col] = v1;
            }
        }
    } else {
        // ---- fused qkv epilogue (tile = 128 tokens x one head region) ----
        const int region = tn >> 4;     // 0=q, 1=k, 2=v
        const int h      = tn & 15;
        const int s0     = tm * 128;
        float* T = (float*)smraw;       // [128][132]
        float* R = T + 128 * 132;       // rstd[128]

#pragma unroll
        for (int nt = 0; nt < 4; nt++) {
            int col = wn * 32 + nt * 8 + c0;
            float bx = __ldg(&bias[tn * 128 + col]);
            float by = __ldg(&bias[tn * 128 + col + 1]);
#pragma unroll
            for (int mt = 0; mt < 4; mt++) {
                int r = wm * 64 + mt * 16 + r0;
                float2 v0, v1;
                v0.x = acc[mt][nt][0] + bx; v0.y = acc[mt][nt][1] + by;
                v1.x = acc[mt][nt][2] + bx; v1.y = acc[mt][nt][3] + by;
                *(float2*)&T[r * 132 + col]       = v0;
                *(float2*)&T[(r + 8) * 132 + col] = v1;
            }
        }
        __syncthreads();

        if (region < 2) {
            {
                int row = tid >> 1, st = (tid & 1) * 64;
                float s = 0.f;
#pragma unroll
                for (int j = 0; j < 64; j += 4) {
                    float4 v = *(const float4*)&T[row * 132 + st + j];
                    s += v.x * v.x + v.y * v.y + v.z * v.z + v.w * v.w;
                }
                s += __shfl_xor_sync(0xffffffffu, s, 1);
                if ((tid & 1) == 0)
                    R[row] = rsqrtf(s * (1.f / 128.f) + EPS);
            }
            __syncthreads();

            {
                const float* w = (region == 0) ? qnw : knw;
                int row = tid >> 1, i0 = (tid & 1) * 32;
                float rs  = R[row];
                float pos = (float)positions[s0 + row];
#pragma unroll 4
                for (int i = i0; i < i0 + 32; i++) {
                    float x1 = T[row * 132 + i]      * rs * w[i];
                    float x2 = T[row * 132 + i + 64] * rs * w[i + 64];
                    float sn, cs2;
                    sincosf(pos * c_invfreq[i], &sn, &cs2);
                    float o1 = x1 * cs2 - x2 * sn;
                    float o2 = x2 * cs2 + x1 * sn;
                    if (region == 0) { o1 *= SCALE_Q; o2 *= SCALE_Q; }
                    T[row * 132 + i]      = o1;
                    T[row * 132 + i + 64] = o2;
                }
            }
            __syncthreads();

            __nv_bfloat16* dst = (region == 0) ? d_qf : d_kf;
#pragma unroll
            for (int l = 0; l < 16; l++) {
                int ci = tid + l * 256;
                int row = ci >> 5, c16 = ci & 31;
                int plane = c16 >> 4, within = c16 & 15;
                float x[8];
                *(float4*)&x[0] = *(const float4*)&T[row * 132 + within * 8];
                *(float4*)&x[4] = *(const float4*)&T[row * 132 + within * 8 + 4];
                __nv_bfloat16 h8[8], l8[8];
#pragma unroll
                for (int q = 0; q < 8; q++) split_bf(x[q], h8[q], l8[q]);
                uint4 outv = plane ? *(uint4*)l8 : *(uint4*)h8;
                *(uint4*)(dst + ((size_t)(s0 + row) * NH + h) * 256 + c16 * 8) = outv;
            }
        } else {
#pragma unroll
            for (int l = 0; l < 16; l++) {
                int ci = tid + l * 256;
                int row = ci >> 5, c16 = ci & 31;
                int plane = c16 >> 4, within = c16 & 15;
                float x[8];
                *(float4*)&x[0] = *(const float4*)&T[row * 132 + within * 8];
                *(float4*)&x[4] = *(const float4*)&T[row * 132 + within * 8 + 4];
                __nv_bfloat16 h8[8], l8[8];
#pragma unroll
                for (int q = 0; q < 8; q++) split_bf(x[q], h8[q], l8[q]);
                uint4 outv = plane ? *(uint4*)l8 : *(uint4*)h8;
                *(uint4*)(d_v2 + ((size_t)(s0 + row) * NH + h) * 256 + c16 * 8) = outv;
            }
        }
    }
}

// ---------------------------------------------------------------------------
// Phase 1 (HMMA): per-64-chunk KV^T, 2-plane smem.
// ---------------------------------------------------------------------------
__global__ __launch_bounds__(256, 2)
void chunk_kv_hmma()
{
    extern __shared__ char sm[];
    const uint32_t sb = smem_u32(sm);
    const int tid = threadIdx.x;
    const int wid = tid >> 5, lid = tid & 31;
    const int wm = wid >> 2, wn = wid & 3;
    const int ch = blockIdx.x, h = blockIdx.y;
    const float slope = c_slopes[h];
    const int t0 = ch * CHK;

    float acc[4][4][4];
#pragma unroll
    for (int i = 0; i < 4; i++)
#pragma unroll
        for (int j = 0; j < 4; j++)
#pragma unroll
            for (int k = 0; k < 4; k++) acc[i][j][k] = 0.f;

#pragma unroll
    for (int l = 0; l < 4; l++) {
        int ci = tid + l * 256;
        int j  = ci >> 4;
        int c8 = ci & 15;
        const __nv_bfloat16* kfrow = d_kf + ((size_t)(t0 + j) * NH + h) * 256;
        uint4 uh = *(const uint4*)(kfrow + c8 * 8);
        uint4 ul = *(const uint4*)(kfrow + 128 + c8 * 8);
        const __nv_bfloat16* ah = (const __nv_bfloat16*)&uh;
        const __nv_bfloat16* al = (const __nv_bfloat16*)&ul;
        float kd = expf(-slope * (float)(CHK - 1 - j));
        __nv_bfloat16 oh[8], ol[8];
#pragma unroll
        for (int q = 0; q < 8; q++) {
            float t = (__bfloat162float(ah[q]) + __bfloat162float(al[q])) * kd;
            split_bf(t, oh[q], ol[q]);
        }
        char* kb = sm + C2_K + c8 * 16;
        *(uint4*)(kb + (size_t)j * 272)        = *(uint4*)oh;
        *(uint4*)(kb + (size_t)(j + 64) * 272) = *(uint4*)ol;
        const __nv_bfloat16* vrow = d_v2 + ((size_t)(t0 + j) * NH + h) * 256;
        uint4 vh = *(const uint4*)(vrow + c8 * 8);
        uint4 vl = *(const uint4*)(vrow + 128 + c8 * 8);
        char* vb = sm + C2_V + c8 * 16;
        *(uint4*)(vb + (size_t)j * 272)        = vh;
        *(uint4*)(vb + (size_t)(j + 64) * 272) = vl;
    }
    __syncthreads();

#pragma unroll
    for (int ks = 0; ks < 192; ks += 16) {
        const int var = (ks < 128) ? ks : ks - 128;   // v [hi|lo|hi]
        const int kbr = (ks < 64) ? ks : ks - 64;     // k [hi|hi|lo]
        uint32_t a[4][4];
#pragma unroll
        for (int mt = 0; mt < 4; mt++) {
            int e0 = wm * 64 + mt * 16;
            uint32_t addr = sb + C2_V +
                (uint32_t)(var + (lid >> 4) * 8 + (lid & 7)) * 272 +
                e0 * 2 + ((lid >> 3) & 1) * 16;
            ldsm_x4_t(a[mt][0], a[mt][1], a[mt][2], a[mt][3], addr);
        }
        uint32_t b[4][2];
#pragma unroll
        for (int nb = 0; nb < 2; nb++) {
            int d0 = wn * 32 + nb * 16;
            uint32_t addr = sb + C2_K +
                (uint32_t)(kbr + ((lid >> 3) & 1) * 8 + (lid & 7)) * 272 +
                d0 * 2 + (lid >> 4) * 16;
            uint32_t r0, r1, r2, r3;
            ldsm_x4_t(r0, r1, r2, r3, addr);
            b[nb * 2][0] = r0;     b[nb * 2][1] = r1;
            b[nb * 2 + 1][0] = r2; b[nb * 2 + 1][1] = r3;
        }
#pragma unroll
        for (int mt = 0; mt < 4; mt++)
#pragma unroll
            for (int nt = 0; nt < 4; nt++)
                mma_bf16(acc[mt][nt], a[mt][0], a[mt][1], a[mt][2], a[mt][3],
                         b[nt][0], b[nt][1]);
    }

    size_t base = ((size_t)(ch * NH + h)) * HD * HD;
#pragma unroll
    for (int mt = 0; mt < 4; mt++) {
        int e = wm * 64 + mt * 16 + (lid >> 2);
#pragma unroll
        for (int nt = 0; nt < 4; nt++) {
            int dd = wn * 32 + nt * 8 + (lid & 3) * 2;
            float2 v0, v1;
            v0.x = acc[mt][nt][0]; v0.y = acc[mt][nt][1];
            v1.x = acc[mt][nt][2]; v1.y = acc[mt][nt][3];
            *(float2*)&d_kvc[base + (size_t)e * HD + dd]       = v0;
            *(float2*)&d_kvc[base + (size_t)(e + 8) * HD + dd] = v1;
        }
    }
}

// ---------------------------------------------------------------------------
// Phase 1b: scan over 128 chunks, emit 2-plane bf16 prefix states.
// ---------------------------------------------------------------------------
__global__ __launch_bounds__(256)
void kv_scan_kernel()
{
    int p  = blockIdx.x * 256 + threadIdx.x;
    int h  = p >> 12;
    int e  = (p >> 5) & 127;
    int d4 = (p & 31) * 4;
    float bd = expf(-c_slopes[h] * (float)CHK);
    float4 st = make_float4(0.f, 0.f, 0.f, 0.f);
#pragma unroll 1
    for (int c = 0; c < NCH; c++) {
        size_t ro = ((size_t)(c * NH + h) * 128 + e);
        __nv_bfloat16 h0, l0, h1, l1, h2, l2, h3, l3;
        split_bf(st.x, h0, l0); split_bf(st.y, h1, l1);
        split_bf(st.z, h2, l2); split_bf(st.w, h3, l3);
        uint2 hp, lp;
        hp.x = pack_bf2(h0, h1); hp.y = pack_bf2(h2, h3);
        lp.x = pack_bf2(l0, l1); lp.y = pack_bf2(l2, l3);
        __nv_bfloat16* orow = d_kvs_f + ro * 256;
        *(uint2*)(orow + d4)       = hp;
        *(uint2*)(orow + 128 + d4) = lp;
        float4 v = *(const float4*)(d_kvc + ro * 128 + d4);
        st.x = bd * st.x + v.x; st.y = bd * st.y + v.y;
        st.z = bd * st.z + v.z; st.w = bd * st.w + v.w;
    }
}

// ---------------------------------------------------------------------------
// Phase 2 (HMMA): fused INTER+SCORES K-loop, then diagonal intra PV.
// Single prefetch phase, 2-plane smem (round-11 layout).
// ---------------------------------------------------------------------------
__global__ __launch_bounds__(256, 1)
void attn_hmma_kernel()
{
    extern __shared__ char sm[];
    const uint32_t sb = smem_u32(sm);
    const int tid = threadIdx.x;
    const int wid = tid >> 5, lid = tid & 31;
    const int wm = wid >> 2, wn = wid & 3;
    const int ch = blockIdx.x, h = blockIdx.y;
    const float slope = c_slopes[h];
    const int s0 = ch * CHK;

    float* tbl = (float*)(sm + A2_TBL);
    if (tid < 65) tbl[tid] = expf(-slope * (float)tid);

    // ---- single prefetch phase: q, state, k, v (disjoint regions) ----
#pragma unroll
    for (int l = 0; l < 8; l++) {
        int ci = tid + l * 256;
        int r = ci >> 5, c16 = ci & 31;
        cp_async16(sb + A2_SQ + r * Q2_ROW + c16 * 16,
                   d_qf + ((size_t)(s0 + r) * NH + h) * 256 + c16 * 8);
    }
    {
        const __nv_bfloat16* kvb = d_kvs_f + ((size_t)(ch * NH + h)) * 128 * 256;
#pragma unroll
        for (int l = 0; l < 16; l++) {
            int ci = tid + l * 256;
            int r = ci >> 5, c16 = ci & 31;
            cp_async16(sb + A2_SS + r * Q2_ROW + c16 * 16,
                       kvb + (size_t)r * 256 + c16 * 8);
        }
    }
#pragma unroll
    for (int l = 0; l < 8; l++) {
        int ci = tid + l * 256;
        int r = ci >> 5, c16 = ci & 31;
        cp_async16(sb + A2_SK + r * Q2_ROW + c16 * 16,
                   d_kf + ((size_t)(s0 + r) * NH + h) * 256 + c16 * 8);
    }
#pragma unroll
    for (int l = 0; l < 8; l++) {
        int ci = tid + l * 256;
        int r = ci >> 5, c16 = ci & 31;
        int plane = c16 >> 4, within = c16 & 15;
        cp_async16(sb + A2_SV + (r + plane * 64) * V2_ROW + within * 16,
                   d_v2 + ((size_t)(s0 + r) * NH + h) * 256 + c16 * 8);
    }
    CP_COMMIT();
    CP_WAIT0();
    __syncthreads();

    // ---- fused INTER + SCORES loop (shared q A-operand) ----
    float acc[2][4][4];
#pragma unroll
    for (int i = 0; i < 2; i++)
#pragma unroll
        for (int j = 0; j < 4; j++)
#pragma unroll
            for (int k = 0; k < 4; k++) acc[i][j][k] = 0.f;

    float accS[2][2][4];
#pragma unroll
    for (int i = 0; i < 2; i++)
#pragma unroll
        for (int j = 0; j < 2; j++)
#pragma unroll
            for (int k = 0; k < 4; k++) accS[i][j][k] = 0.f;

    const int bg = lid >> 3;
#pragma unroll
    for (int ks = 0; ks < 384; ks += 16) {
        const int aks = (ks < 256) ? ks : ks - 256;
        const int bks = (ks < 256) ? (ks & 127) : (ks - 128);
        uint32_t a[2][4];
#pragma unroll
        for (int mt = 0; mt < 2; mt++) {
            uint32_t addr = sb + A2_SQ +
                (uint32_t)(wm * 32 + mt * 16 + (lid & 15)) * Q2_ROW +
                aks * 2 + (lid >> 4) * 16;
            ldsm_x4(a[mt][0], a[mt][1], a[mt][2], a[mt][3], addr);
        }
        // INTER B: state rows
        uint32_t b[4][2];
#pragma unroll
        for (int nb = 0; nb < 2; nb++) {
            int n0 = wn * 32 + nb * 16;
            uint32_t addr = sb + A2_SS +
                (uint32_t)(n0 + (bg >> 1) * 8 + (lid & 7)) * Q2_ROW +
                bks * 2 + (bg & 1) * 16;
            uint32_t r0, r1, r2, r3;
            ldsm_x4(r0, r1, r2, r3, addr);
            b[nb * 2][0] = r0;     b[nb * 2][1] = r1;
            b[nb * 2 + 1][0] = r2; b[nb * 2 + 1][1] = r3;
        }
        // SCORES B: k rows
        uint32_t kb0, kb1, kb2, kb3;
        {
            int n0 = wn * 16;
            uint32_t addr = sb + A2_SK +
                (uint32_t)(n0 + (bg >> 1) * 8 + (lid & 7)) * Q2_ROW +
                bks * 2 + (bg & 1) * 16;
            ldsm_x4(kb0, kb1, kb2, kb3, addr);
        }
#pragma unroll
        for (int mt = 0; mt < 2; mt++) {
#pragma unroll
            for (int nt = 0; nt < 4; nt++)
                mma_bf16(acc[mt][nt], a[mt][0], a[mt][1], a[mt][2], a[mt][3],
                         b[nt][0], b[nt][1]);
            mma_bf16(accS[mt][0], a[mt][0], a[mt][1], a[mt][2], a[mt][3], kb0, kb1);
            mma_bf16(accS[mt][1], a[mt][0], a[mt][1], a[mt][2], a[mt][3], kb2, kb3);
        }
    }

    // qdecay row scaling on inter output
#pragma unroll
    for (int mt = 0; mt < 2; mt++) {
        int r = wm * 32 + mt * 16 + (lid >> 2);
        float q0 = tbl[r + 1];
        float q1 = tbl[r + 9];
#pragma unroll
        for (int nt = 0; nt < 4; nt++) {
            acc[mt][nt][0] *= q0; acc[mt][nt][1] *= q0;
            acc[mt][nt][2] *= q1; acc[mt][nt][3] *= q1;
        }
    }

    // ---- mask + decay + 2-plane P fold (hi cols 0-63, lo cols 64-127) ----
#pragma unroll
    for (int mt = 0; mt < 2; mt++) {
        int r = wm * 32 + mt * 16 + (lid >> 2);
#pragma unroll
        for (int nt = 0; nt < 2; nt++) {
            int cc = wn * 16 + nt * 8 + (lid & 3) * 2;
            int d00 = r - cc;
            float v00 = (d00 >= 0) ? accS[mt][nt][0] * tbl[d00]     : 0.f;
            float v01 = (d00 >= 1) ? accS[mt][nt][1] * tbl[d00 - 1] : 0.f;
            int d10 = d00 + 8;
            float v10 = (d10 >= 0) ? accS[mt][nt][2] * tbl[d10]     : 0.f;
            float v11 = (d10 >= 1) ? accS[mt][nt][3] * tbl[d10 - 1] : 0.f;
            __nv_bfloat16 h00, l00, h01, l01, h10, l10, h11, l11;
            split_bf(v00, h00, l00); split_bf(v01, h01, l01);
            split_bf(v10, h10, l10); split_bf(v11, h11, l11);
            char* b0p = sm + A2_SP + r * Q2_ROW + cc * 2;
            *(uint32_t*)(b0p)       = pack_bf2(h00, h01);
            *(uint32_t*)(b0p + 128) = pack_bf2(l00, l01);
            char* b1p = b0p + 8 * Q2_ROW;
            *(uint32_t*)(b1p)       = pack_bf2(h10, h11);
            *(uint32_t*)(b1p + 128) = pack_bf2(l10, l11);
        }
    }
    __syncthreads();

    // ---- PV: O += P'(64x192 logical) @ v'(trans) ----
#pragma unroll
    for (int ks = 0; ks < 192; ks += 16) {
        const int aks = (ks < 128) ? ks : ks - 128;      // P [hi|lo|hi], plane=64
        const int vbr = (ks < 64) ? ks : ks - 64;        // v [hi|hi|lo] rows
        uint32_t a[2][4];
#pragma unroll
        for (int mt = 0; mt < 2; mt++) {
            uint32_t addr = sb + A2_SP +
                (uint32_t)(wm * 32 + mt * 16 + (lid & 15)) * Q2_ROW +
                aks * 2 + (lid >> 4) * 16;
            ldsm_x4(a[mt][0], a[mt][1], a[mt][2], a[mt][3], addr);
        }
        uint32_t b[4][2];
#pragma unroll
        for (int nb = 0; nb < 2; nb++) {
            int e0 = wn * 32 + nb * 16;
            uint32_t addr = sb + A2_SV +
                (uint32_t)(vbr + ((lid >> 3) & 1) * 8 + (lid & 7)) * V2_ROW +
                e0 * 2 + (lid >> 4) * 16;
            uint32_t r0, r1, r2, r3;
            ldsm_x4_t(r0, r1, r2, r3, addr);
            b[nb * 2][0] = r0;     b[nb * 2][1] = r1;
            b[nb * 2 + 1][0] = r2; b[nb * 2 + 1][1] = r3;
        }
#pragma unroll
        for (int mt = 0; mt < 2; mt++)
#pragma unroll
            for (int nt = 0; nt < 4; nt++)
                mma_bf16(acc[mt][nt], a[mt][0], a[mt][1], a[mt][2], a[mt][3],
                         b[nt][0], b[nt][1]);
    }

    // store O
#pragma unroll
    for (int mt = 0; mt < 2; mt++) {
        int r = wm * 32 + mt * 16 + (lid >> 2);
#pragma unroll
        for (int nt = 0; nt < 4; nt++) {
            int col = wn * 32 + nt * 8 + (lid & 3) * 2;
            float2 v0, v1;
            v0.x = acc[mt][nt][0]; v0.y = acc[mt][nt][1];
            v1.x = acc[mt][nt][2]; v1.y = acc[mt][nt][3];
            *(float2*)&d_attn[(size_t)(s0 + r) * HDTOT + h * HD + col]     = v0;
            *(float2*)&d_attn[(size_t)(s0 + r + 8) * HDTOT + h * HD + col] = v1;
        }
    }
}

// ---------------------------------------------------------------------------
// Group-RMSNorm + sigmoid gating -> 3-plane split-bf16 y (A pattern)
// ---------------------------------------------------------------------------
__global__ __launch_bounds__(256)
void gate_kernel(const float* __restrict__ gnw)
{
    int s = blockIdx.x;
    int t = threadIdx.x;
    size_t base = (size_t)s * HDTOT + t * 8;

    float a[8];
    *(float4*)&a[0] = *(const float4*)&d_attn[base];
    *(float4*)&a[4] = *(const float4*)&d_attn[base + 4];

    float ss = 0.f;
#pragma unroll
    for (int j = 0; j < 8; j++) ss += a[j] * a[j];
#pragma unroll
    for (int off = 16; off > 0; off >>= 1)
        ss += __shfl_xor_sync(0xffffffffu, ss, off);
    float rstd = rsqrtf(ss * (1.f / 256.f) + EPS);

    float gv[8];
    *(float4*)&gv[0] = *(const float4*)&d_g[base];
    *(float4*)&gv[4] = *(const float4*)&d_g[base + 4];

    __nv_bfloat16 hi[8], lo[8];
#pragma unroll
    for (int j = 0; j < 8; j++) {
        float sig = 1.f / (1.f + expf(-gv[j]));
        float y = a[j] * rstd * gnw[t * 8 + j] * sig;
        split_bf(y, hi[j], lo[j]);
    }
    __nv_bfloat16* dst = d_y_s + (size_t)s * GK + t * 8;
    *(uint4*)(dst)        = *(uint4*)hi;
    *(uint4*)(dst + 2048) = *(uint4*)lo;
    *(uint4*)(dst + 4096) = *(uint4*)hi;
}

// ---------------------------------------------------------------------------
// Launch — round-11 proven schedule: side stream runs g/dense splits + gate
// GEMM concurrent with the qkv split+GEMM window; join before gate_kernel.
// ---------------------------------------------------------------------------
extern "C" void kernel_launch(void* const* d_in, const int* in_sizes, int n_in,
                              void* d_out, int out_size)
{
    const float* hs     = (const float*)d_in[0];
    const int*   pos    = (const int*)  d_in[1];
    const float* qkv_w  = (const float*)d_in[2];
    const float* qkv_b  = (const float*)d_in[3];
    const float* qnw    = (const float*)d_in[4];
    const float* knw    = (const float*)d_in[5];
    const float* g_w    = (const float*)d_in[6];
    const float* gnw    = (const float*)d_in[7];
    const float* dens_w = (const float*)d_in[8];
    float* out = (float*)d_out;

    float *p_g;
    __nv_bfloat16 *p_hs_s, *p_qkvw_s, *p_gw_s, *p_dw_s, *p_y_s;
    cudaGetSymbolAddress((void**)&p_g,      d_g);
    cudaGetSymbolAddress((void**)&p_hs_s,   d_hs_s);
    cudaGetSymbolAddress((void**)&p_qkvw_s, d_qkvw_s);
    cudaGetSymbolAddress((void**)&p_gw_s,   d_gw_s);
    cudaGetSymbolAddress((void**)&p_dw_s,   d_dw_s);
    cudaGetSymbolAddress((void**)&p_y_s,    d_y_s);

    cudaFuncSetAttribute(hmma_gemm<0>,
                         cudaFuncAttributeMaxDynamicSharedMemorySize, GEMM_SMEM);
    cudaFuncSetAttribute(hmma_gemm<1>,
                         cudaFuncAttributeMaxDynamicSharedMemorySize, GEMM_SMEM);
    cudaFuncSetAttribute(attn_hmma_kernel,
                         cudaFuncAttributeMaxDynamicSharedMemorySize, ATTN_SMEM);
    cudaFuncSetAttribute(chunk_kv_hmma,
                         cudaFuncAttributeMaxDynamicSharedMemorySize, CHUNK_SMEM);

    static cudaStream_t s_side = nullptr;
    static cudaEvent_t  ev_fork = nullptr, ev_join = nullptr;
    if (s_side == nullptr) {
        cudaStreamCreateWithFlags(&s_side, cudaStreamNonBlocking);
        cudaEventCreateWithFlags(&ev_fork, cudaEventDisableTiming);
        cudaEventCreateWithFlags(&ev_join, cudaEventDisableTiming);
    }

    init_tables_kernel<<<1, 64>>>();

    split_kernel<<<(S_LEN * HID) / (256 * 8), 256>>>(hs, p_hs_s, 1);

    // fork: side stream handles g/dense weight splits + gate GEMM
    cudaEventRecord(ev_fork, 0);
    cudaStreamWaitEvent(s_side, ev_fork, 0);

    split_kernel<<<(HDTOT * HID) / (256 * 8), 256, 0, s_side>>>(g_w,    p_gw_s, 0);
    split_kernel<<<(HDTOT * HID) / (256 * 8), 256, 0, s_side>>>(dens_w, p_dw_s, 0);
    hmma_gemm<0><<<(S_LEN / 128) * (HDTOT / 128), 256, GEMM_SMEM, s_side>>>(
        p_hs_s, p_gw_s, nullptr, p_g, HDTOT, nullptr, nullptr, nullptr);
    cudaEventRecord(ev_join, s_side);

    // main: qkv split + GEMM (fused epilogue) -> attention chain
    split_kernel<<<(QKV_N * HID) / (256 * 8), 256>>>(qkv_w, p_qkvw_s, 0);
    hmma_gemm<1><<<(S_LEN / 128) * (QKV_N / 128), 256, GEMM_SMEM>>>(
        p_hs_s, p_qkvw_s, qkv_b, nullptr, QKV_N, pos, qnw, knw);

    chunk_kv_hmma<<<dim3(NCH, NH), 256, CHUNK_SMEM>>>();
    kv_scan_kernel<<<256, 256>>>();
    attn_hmma_kernel<<<dim3(NCH, NH), 256, ATTN_SMEM>>>();

    cudaStreamWaitEvent(0, ev_join, 0);

    gate_kernel<<<S_LEN, 256>>>(gnw);

    hmma_gemm<0><<<(S_LEN / 128) * (HDTOT / 128), 256, GEMM_SMEM>>>(
        p_y_s, p_dw_s, nullptr, out, HDTOT, nullptr, nullptr, nullptr);
}